// round 1
// baseline (speedup 1.0000x reference)
#include <cuda_runtime.h>
#include <math.h>

#define EPS 1e-3f
#define NMAX 50048

// ---------------- device scratch (static; no allocation) ----------------
__device__ float g_agg[NMAX * 64];   // segment sums [N,64]
__device__ float g_cnt[NMAX];        // segment counts
__device__ float g_Wm1[64 * 64],  g_cm1[64];
__device__ float g_Wm2[64 * 64],  g_cm2[64];
__device__ float g_Wu1[128 * 64], g_cu1[64];
__device__ float g_Wu2[64 * 64],  g_cu2[64];

__device__ __forceinline__ float gelu_f(float x) {
    return 0.5f * x * (1.0f + erff(x * 0.70710678118654752440f));
}

// ---------------- zero accumulators ----------------
__global__ void zero_kernel(int N) {
    int total = N * 64 + N;
    for (int i = blockIdx.x * blockDim.x + threadIdx.x; i < total;
         i += gridDim.x * blockDim.x) {
        if (i < N * 64) g_agg[i] = 0.0f;
        else            g_cnt[i - N * 64] = 0.0f;
    }
}

// ---------------- fold BN into weights/biases ----------------
__global__ void prep_kernel(
    const float* mg1, const float* mb1, const float* mm1, const float* mv1,
    const float* mW1, const float* mc1,
    const float* mg2, const float* mb2, const float* mm2, const float* mv2,
    const float* mW2, const float* mc2,
    const float* ug1, const float* ub1, const float* um1, const float* uv1,
    const float* uW1, const float* uc1,
    const float* ug2, const float* ub2, const float* um2, const float* uv2,
    const float* uW2, const float* uc2)
{
    int tid = threadIdx.x;  // 256 threads, 1 block
    for (int idx = tid; idx < 64 * 64; idx += 256) {
        int k = idx >> 6;
        g_Wm1[idx] = mg1[k] * rsqrtf(mv1[k] + EPS) * mW1[idx];
        g_Wm2[idx] = mg2[k] * rsqrtf(mv2[k] + EPS) * mW2[idx];
        g_Wu2[idx] = ug2[k] * rsqrtf(uv2[k] + EPS) * uW2[idx];
    }
    for (int idx = tid; idx < 128 * 64; idx += 256) {
        int k = idx >> 6;
        g_Wu1[idx] = ug1[k] * rsqrtf(uv1[k] + EPS) * uW1[idx];
    }
    if (tid < 64) {
        float s1 = 0.f, s2 = 0.f, s4 = 0.f;
        for (int k = 0; k < 64; k++) {
            float sc;
            sc = mg1[k] * rsqrtf(mv1[k] + EPS);
            s1 += (mb1[k] - mm1[k] * sc) * mW1[k * 64 + tid];
            sc = mg2[k] * rsqrtf(mv2[k] + EPS);
            s2 += (mb2[k] - mm2[k] * sc) * mW2[k * 64 + tid];
            sc = ug2[k] * rsqrtf(uv2[k] + EPS);
            s4 += (ub2[k] - um2[k] * sc) * uW2[k * 64 + tid];
        }
        float s3 = 0.f;
        for (int k = 0; k < 128; k++) {
            float sc = ug1[k] * rsqrtf(uv1[k] + EPS);
            s3 += (ub1[k] - um1[k] * sc) * uW1[k * 64 + tid];
        }
        g_cm1[tid] = mc1[tid] + s1;
        g_cm2[tid] = mc2[tid] + s2;
        g_cu1[tid] = uc1[tid] + s3;
        g_cu2[tid] = uc2[tid] + s4;
    }
}

// ---------------- tile GEMM: [64,K] @ [K,64] -> gelu -> [64,64] ----------------
// A: smem, leading dim LDA (padded). W: smem K x 64 row-major (float4 aligned).
// out may alias A (register accumulation + syncthreads).
template <int K, int LDA, int LDO>
__device__ __forceinline__ void gemm_tile(const float* __restrict__ A,
                                          const float* __restrict__ W,
                                          const float* __restrict__ bias,
                                          float* __restrict__ out, int tid)
{
    const int tx = tid & 15, ty = tid >> 4;
    const int c0 = tx << 2, r0 = ty << 2;
    float acc[4][4];
#pragma unroll
    for (int j = 0; j < 4; j++)
#pragma unroll
        for (int i = 0; i < 4; i++) acc[j][i] = 0.0f;
    const float* Ap = A + r0 * LDA;
#pragma unroll 8
    for (int k = 0; k < K; k++) {
        float4 b = *(const float4*)(W + (k << 6) + c0);
        float a0 = Ap[k];
        float a1 = Ap[LDA + k];
        float a2 = Ap[2 * LDA + k];
        float a3 = Ap[3 * LDA + k];
        acc[0][0] += a0 * b.x; acc[0][1] += a0 * b.y; acc[0][2] += a0 * b.z; acc[0][3] += a0 * b.w;
        acc[1][0] += a1 * b.x; acc[1][1] += a1 * b.y; acc[1][2] += a1 * b.z; acc[1][3] += a1 * b.w;
        acc[2][0] += a2 * b.x; acc[2][1] += a2 * b.y; acc[2][2] += a2 * b.z; acc[2][3] += a2 * b.w;
        acc[3][0] += a3 * b.x; acc[3][1] += a3 * b.y; acc[3][2] += a3 * b.z; acc[3][3] += a3 * b.w;
    }
    __syncthreads();
#pragma unroll
    for (int j = 0; j < 4; j++)
#pragma unroll
        for (int i = 0; i < 4; i++)
            out[(r0 + j) * LDO + c0 + i] = gelu_f(acc[j][i] + bias[c0 + i]);
    __syncthreads();
}

// ---------------- fused edge pipeline ----------------
// smem layout (floats): Wm1[4096] Wm2[4096] We1[4096] We2[4096]
//                       A[64*65] B[64*65] bias[256] | src[64] dst[64] (ints)
#define EDGE_SMEM_BYTES ((4 * 4096 + 2 * 64 * 65 + 256) * 4 + 128 * 4)

__global__ void __launch_bounds__(256, 2)
edge_kernel(const float* __restrict__ nf, const float* __restrict__ ef,
            const int* __restrict__ src, const int* __restrict__ dst,
            const float* __restrict__ We1, const float* __restrict__ ec1,
            const float* __restrict__ We2, const float* __restrict__ ec2,
            int E)
{
    extern __shared__ float sm[];
    float* sWm1 = sm;
    float* sWm2 = sWm1 + 4096;
    float* sWe1 = sWm2 + 4096;
    float* sWe2 = sWe1 + 4096;
    float* sA   = sWe2 + 4096;      // 64*65
    float* sB   = sA + 64 * 65;     // 64*65
    float* sb   = sB + 64 * 65;     // 256 biases [m1|m2|e1|e2]
    int*   sSrc = (int*)(sb + 256);
    int*   sDst = sSrc + 64;

    const int tid = threadIdx.x;
    for (int i = tid; i < 4096; i += 256) {
        sWm1[i] = g_Wm1[i];
        sWm2[i] = g_Wm2[i];
        sWe1[i] = We1[i];
        sWe2[i] = We2[i];
    }
    if (tid < 64) {
        sb[tid]       = g_cm1[tid];
        sb[64 + tid]  = g_cm2[tid];
        sb[128 + tid] = ec1[tid];
        sb[192 + tid] = ec2[tid];
    }
    __syncthreads();

    const int ntiles = (E + 63) >> 6;
    for (int t = blockIdx.x; t < ntiles; t += gridDim.x) {
        const int base = t << 6;
        const int valid = min(64, E - base);
        if (tid < 64) {
            int e = base + min(tid, valid - 1);
            sSrc[tid] = src[e];
            sDst[tid] = dst[e];
        }
        __syncthreads();
        // stage: gather nbr rows + edge feats (float4)
        for (int idx = tid; idx < 1024; idx += 256) {
            int r = idx >> 4, q = idx & 15;
            float4 v, e4;
            if (r < valid) {
                v  = __ldg((const float4*)nf + (size_t)sDst[r] * 16 + q);
                e4 = __ldg((const float4*)ef + (size_t)(base + r) * 16 + q);
            } else {
                v = make_float4(0.f, 0.f, 0.f, 0.f);
                e4 = v;
            }
            float* p = sA + r * 65 + (q << 2);
            p[0] = v.x; p[1] = v.y; p[2] = v.z; p[3] = v.w;
            float* pe = sB + r * 65 + (q << 2);
            pe[0] = e4.x; pe[1] = e4.y; pe[2] = e4.z; pe[3] = e4.w;
        }
        __syncthreads();

        gemm_tile<64, 65, 65>(sA, sWm1, sb,       sA, tid);
        gemm_tile<64, 65, 65>(sA, sWm2, sb + 64,  sA, tid);
        gemm_tile<64, 65, 65>(sB, sWe1, sb + 128, sB, tid);
        gemm_tile<64, 65, 65>(sB, sWe2, sb + 192, sB, tid);

        // gate + vector scatter-add
        for (int idx = tid; idx < 1024; idx += 256) {
            int r = idx >> 4, q = idx & 15;
            if (r < valid) {
                const float* pa = sA + r * 65 + (q << 2);
                const float* pb = sB + r * 65 + (q << 2);
                float x0 = pa[0] * pb[0], x1 = pa[1] * pb[1];
                float x2 = pa[2] * pb[2], x3 = pa[3] * pb[3];
                float* addr = g_agg + (size_t)sSrc[r] * 64 + (q << 2);
                asm volatile("red.global.add.v4.f32 [%0], {%1,%2,%3,%4};"
                             :: "l"(addr), "f"(x0), "f"(x1), "f"(x2), "f"(x3)
                             : "memory");
            }
        }
        if (tid < valid) atomicAdd(&g_cnt[sSrc[tid]], 1.0f);
        __syncthreads();
    }
}

// ---------------- node update ----------------
// smem floats: W1[8192] W2[4096] A[64*129] H[64*65] b1[64] b2[64]
#define NODE_SMEM_BYTES ((8192 + 4096 + 64 * 129 + 64 * 65 + 128) * 4)

__global__ void __launch_bounds__(256, 2)
node_kernel(const float* __restrict__ nf, float* __restrict__ out, int N)
{
    extern __shared__ float sm[];
    float* sW1 = sm;                 // 128x64
    float* sW2 = sW1 + 8192;         // 64x64
    float* sA  = sW2 + 4096;         // 64 x 129
    float* sH  = sA + 64 * 129;      // 64 x 65
    float* sb1 = sH + 64 * 65;
    float* sb2 = sb1 + 64;

    const int tid = threadIdx.x;
    for (int i = tid; i < 8192; i += 256) sW1[i] = g_Wu1[i];
    for (int i = tid; i < 4096; i += 256) sW2[i] = g_Wu2[i];
    if (tid < 64) { sb1[tid] = g_cu1[tid]; sb2[tid] = g_cu2[tid]; }
    __syncthreads();

    const int ntiles = (N + 63) >> 6;
    for (int t = blockIdx.x; t < ntiles; t += gridDim.x) {
        const int base = t << 6;
        const int valid = min(64, N - base);
        // stage concat [node_feats | agg/max(cnt,1)] : 64 rows x 32 float4
        for (int idx = tid; idx < 2048; idx += 256) {
            int r = idx >> 5, q = idx & 31;
            float* p = sA + r * 129 + (q << 2);
            if (r < valid) {
                int n = base + r;
                if (q < 16) {
                    float4 v = __ldg((const float4*)nf + (size_t)n * 16 + q);
                    p[0] = v.x; p[1] = v.y; p[2] = v.z; p[3] = v.w;
                } else {
                    float inv = 1.0f / fmaxf(g_cnt[n], 1.0f);
                    float4 v = *((const float4*)g_agg + (size_t)n * 16 + (q - 16));
                    p[0] = v.x * inv; p[1] = v.y * inv;
                    p[2] = v.z * inv; p[3] = v.w * inv;
                }
            } else {
                p[0] = 0.f; p[1] = 0.f; p[2] = 0.f; p[3] = 0.f;
            }
        }
        __syncthreads();

        gemm_tile<128, 129, 65>(sA, sW1, sb1, sH, tid);

        // final GEMM: sH[64,64] @ W2 -> gelu -> global
        {
            const int tx = tid & 15, ty = tid >> 4;
            const int c0 = tx << 2, r0 = ty << 2;
            float acc[4][4];
#pragma unroll
            for (int j = 0; j < 4; j++)
#pragma unroll
                for (int i = 0; i < 4; i++) acc[j][i] = 0.0f;
            const float* Ap = sH + r0 * 65;
#pragma unroll 8
            for (int k = 0; k < 64; k++) {
                float4 b = *(const float4*)(sW2 + (k << 6) + c0);
                float a0 = Ap[k], a1 = Ap[65 + k], a2 = Ap[130 + k], a3 = Ap[195 + k];
                acc[0][0] += a0 * b.x; acc[0][1] += a0 * b.y; acc[0][2] += a0 * b.z; acc[0][3] += a0 * b.w;
                acc[1][0] += a1 * b.x; acc[1][1] += a1 * b.y; acc[1][2] += a1 * b.z; acc[1][3] += a1 * b.w;
                acc[2][0] += a2 * b.x; acc[2][1] += a2 * b.y; acc[2][2] += a2 * b.z; acc[2][3] += a2 * b.w;
                acc[3][0] += a3 * b.x; acc[3][1] += a3 * b.y; acc[3][2] += a3 * b.z; acc[3][3] += a3 * b.w;
            }
#pragma unroll
            for (int j = 0; j < 4; j++) {
                int r = r0 + j;
                if (r < valid) {
#pragma unroll
                    for (int i = 0; i < 4; i++)
                        out[(size_t)(base + r) * 64 + c0 + i] =
                            gelu_f(acc[j][i] + sb2[c0 + i]);
                }
            }
        }
        __syncthreads();
    }
}

// ---------------- launch ----------------
extern "C" void kernel_launch(void* const* d_in, const int* in_sizes, int n_in,
                              void* d_out, int out_size)
{
    // Detect input ordering: dict order has src (size E~8e5) at index 2;
    // reference-signature order has m_g1 (size 64) at index 2.
    int pi;
    const int *src, *dst;
    int E;
    if (in_sizes[2] > 1000) {            // dict order: node, edge, src, dst, params...
        src = (const int*)d_in[2];
        dst = (const int*)d_in[3];
        E = in_sizes[2];
        pi = 4;
    } else {                              // reference order: params..., src, dst
        pi = 2;
        src = (const int*)d_in[30];
        dst = (const int*)d_in[31];
        E = in_sizes[30];
    }
    const float* nf = (const float*)d_in[0];
    const float* ef = (const float*)d_in[1];
    const int N = in_sizes[0] / 64;

    const float* P[28];
    for (int i = 0; i < 28; i++) P[i] = (const float*)d_in[pi + i];
    // P: 0..5 m1(g,b,mu,v,W,c) 6..11 m2 12..15 eW1,ec1,eW2,ec2 16..21 u1 22..27 u2

    cudaFuncSetAttribute(edge_kernel, cudaFuncAttributeMaxDynamicSharedMemorySize,
                         EDGE_SMEM_BYTES);
    cudaFuncSetAttribute(node_kernel, cudaFuncAttributeMaxDynamicSharedMemorySize,
                         NODE_SMEM_BYTES);

    zero_kernel<<<512, 256>>>(N);
    prep_kernel<<<1, 256>>>(P[0], P[1], P[2], P[3], P[4], P[5],
                            P[6], P[7], P[8], P[9], P[10], P[11],
                            P[16], P[17], P[18], P[19], P[20], P[21],
                            P[22], P[23], P[24], P[25], P[26], P[27]);
    edge_kernel<<<304, 256, EDGE_SMEM_BYTES>>>(nf, ef, src, dst,
                                               P[12], P[13], P[14], P[15], E);
    node_kernel<<<304, 256, NODE_SMEM_BYTES>>>(nf, (float*)d_out, N);
}

// round 2
// speedup vs baseline: 1.4720x; 1.4720x over previous
#include <cuda_runtime.h>
#include <math.h>

#define EPS 1e-3f
#define NMAX 50048

typedef unsigned long long ull;

// ---------------- device scratch (static; no allocation) ----------------
__device__ float g_agg[NMAX * 64];   // segment sums [N,64]
__device__ float g_cnt[NMAX];        // segment counts
__device__ float g_msg[NMAX * 64];   // precomputed per-node message MLP output

// BN-folded / transposed weights (WT[c][k], row stride padded)
__device__ float g_Wm1T[64 * 68],  g_cm1[64];
__device__ float g_Wm2T[64 * 68],  g_cm2[64];
__device__ float g_We1T[64 * 68];
__device__ float g_We2T[64 * 68];
__device__ float g_Wu1T[64 * 132], g_cu1[64];
__device__ float g_Wu2T[64 * 68],  g_cu2[64];

__device__ __forceinline__ float gelu_f(float x) {
    return 0.5f * x * (1.0f + erff(x * 0.70710678118654752440f));
}

__device__ __forceinline__ void ffma2(ull& acc, ull a, ull b) {
    asm("fma.rn.f32x2 %0, %1, %2, %0;" : "+l"(acc) : "l"(a), "l"(b));
}

__device__ __forceinline__ float2 unpack_f2(ull v) {
    float2 r;
    asm("mov.b64 {%0, %1}, %2;" : "=f"(r.x), "=f"(r.y) : "l"(v));
    return r;
}

// ---------------- zero accumulators ----------------
__global__ void zero_kernel(int N) {
    int total = N * 64 + N;
    for (int i = blockIdx.x * blockDim.x + threadIdx.x; i < total;
         i += gridDim.x * blockDim.x) {
        if (i < N * 64) g_agg[i] = 0.0f;
        else            g_cnt[i - N * 64] = 0.0f;
    }
}

// ---------------- fold BN into weights, transpose all weights ----------------
__global__ void prep_kernel(
    const float* mg1, const float* mb1, const float* mm1, const float* mv1,
    const float* mW1, const float* mc1,
    const float* mg2, const float* mb2, const float* mm2, const float* mv2,
    const float* mW2, const float* mc2,
    const float* eW1, const float* eW2,
    const float* ug1, const float* ub1, const float* um1, const float* uv1,
    const float* uW1, const float* uc1,
    const float* ug2, const float* ub2, const float* um2, const float* uv2,
    const float* uW2, const float* uc2)
{
    int tid = threadIdx.x;  // 256 threads, 1 block
    for (int idx = tid; idx < 64 * 64; idx += 256) {
        int c = idx >> 6, k = idx & 63;
        g_Wm1T[c * 68 + k] = mg1[k] * rsqrtf(mv1[k] + EPS) * mW1[k * 64 + c];
        g_Wm2T[c * 68 + k] = mg2[k] * rsqrtf(mv2[k] + EPS) * mW2[k * 64 + c];
        g_Wu2T[c * 68 + k] = ug2[k] * rsqrtf(uv2[k] + EPS) * uW2[k * 64 + c];
        g_We1T[c * 68 + k] = eW1[k * 64 + c];
        g_We2T[c * 68 + k] = eW2[k * 64 + c];
    }
    for (int idx = tid; idx < 64 * 128; idx += 256) {
        int c = idx >> 7, k = idx & 127;
        g_Wu1T[c * 132 + k] = ug1[k] * rsqrtf(uv1[k] + EPS) * uW1[k * 64 + c];
    }
    if (tid < 64) {
        float s1 = 0.f, s2 = 0.f, s4 = 0.f;
        for (int k = 0; k < 64; k++) {
            float sc;
            sc = mg1[k] * rsqrtf(mv1[k] + EPS);
            s1 += (mb1[k] - mm1[k] * sc) * mW1[k * 64 + tid];
            sc = mg2[k] * rsqrtf(mv2[k] + EPS);
            s2 += (mb2[k] - mm2[k] * sc) * mW2[k * 64 + tid];
            sc = ug2[k] * rsqrtf(uv2[k] + EPS);
            s4 += (ub2[k] - um2[k] * sc) * uW2[k * 64 + tid];
        }
        float s3 = 0.f;
        for (int k = 0; k < 128; k++) {
            float sc = ug1[k] * rsqrtf(uv1[k] + EPS);
            s3 += (ub1[k] - um1[k] * sc) * uW1[k * 64 + tid];
        }
        g_cm1[tid] = mc1[tid] + s1;
        g_cm2[tid] = mc2[tid] + s2;
        g_cu1[tid] = uc1[tid] + s3;
        g_cu2[tid] = uc2[tid] + s4;
    }
}

// ---------------- FFMA2 tile GEMM ----------------
// [64, K] @ [K, 64] -> +bias -> gelu -> out [64, 64]
// A: smem row-major, stride LDA (LDA/4 odd => conflict-free strided-row LDS.128)
// WT: smem, W transposed: WT[c*LDW + k]
// 256 threads; thread (rg = tid&15, cg = tid>>4) computes rows rg+16i, cols cg+16j.
// k-pairs packed in f32x2: zero packing instructions.
// out may alias A (register accumulation + internal syncthreads).
template <int K, int LDA, int LDW, int LDO>
__device__ __forceinline__ void gemm_f2(const float* __restrict__ A,
                                        const float* __restrict__ WT,
                                        const float* __restrict__ bias,
                                        float* __restrict__ out, int tid)
{
    const int rg = tid & 15, cg = tid >> 4;
    ull acc[4][4];
#pragma unroll
    for (int i = 0; i < 4; i++)
#pragma unroll
        for (int j = 0; j < 4; j++) acc[i][j] = 0ull;

#pragma unroll 4
    for (int k = 0; k < K; k += 4) {
        ulonglong2 a[4], w[4];
#pragma unroll
        for (int i = 0; i < 4; i++)
            a[i] = *(const ulonglong2*)(A + (rg + 16 * i) * LDA + k);
#pragma unroll
        for (int j = 0; j < 4; j++)
            w[j] = *(const ulonglong2*)(WT + (cg + 16 * j) * LDW + k);
#pragma unroll
        for (int i = 0; i < 4; i++)
#pragma unroll
            for (int j = 0; j < 4; j++) {
                ffma2(acc[i][j], a[i].x, w[j].x);
                ffma2(acc[i][j], a[i].y, w[j].y);
            }
    }
    __syncthreads();
#pragma unroll
    for (int i = 0; i < 4; i++)
#pragma unroll
        for (int j = 0; j < 4; j++) {
            float2 p = unpack_f2(acc[i][j]);
            out[(rg + 16 * i) * LDO + cg + 16 * j] =
                gelu_f(p.x + p.y + bias[cg + 16 * j]);
        }
    __syncthreads();
}

// ---------------- per-node message MLP precompute ----------------
// smem floats: Wm1T[4352] Wm2T[4352] A[4352] bias[128]
#define MSG_SMEM_BYTES ((3 * 4352 + 128) * 4)

__global__ void __launch_bounds__(256, 2)
msg_kernel(const float* __restrict__ nf, int N)
{
    extern __shared__ float sm[];
    float* sW1 = sm;
    float* sW2 = sW1 + 4352;
    float* sA  = sW2 + 4352;
    float* sb  = sA + 4352;

    const int tid = threadIdx.x;
    for (int i = tid; i < 4352; i += 256) {
        sW1[i] = g_Wm1T[i];
        sW2[i] = g_Wm2T[i];
    }
    if (tid < 64) { sb[tid] = g_cm1[tid]; sb[64 + tid] = g_cm2[tid]; }
    __syncthreads();

    const int ntiles = (N + 63) >> 6;
    for (int t = blockIdx.x; t < ntiles; t += gridDim.x) {
        const int base = t << 6;
        const int valid = min(64, N - base);
        for (int idx = tid; idx < 1024; idx += 256) {
            int r = idx >> 4, q = idx & 15;
            float4 v = (r < valid)
                ? __ldg((const float4*)nf + (size_t)(base + r) * 16 + q)
                : make_float4(0.f, 0.f, 0.f, 0.f);
            float* p = sA + r * 68 + (q << 2);
            p[0] = v.x; p[1] = v.y; p[2] = v.z; p[3] = v.w;
        }
        __syncthreads();

        gemm_f2<64, 68, 68, 68>(sA, sW1, sb,      sA, tid);
        gemm_f2<64, 68, 68, 68>(sA, sW2, sb + 64, sA, tid);

        for (int idx = tid; idx < 1024; idx += 256) {
            int r = idx >> 4, q = idx & 15;
            if (r < valid) {
                const float* p = sA + r * 68 + (q << 2);
                ((float4*)g_msg)[(size_t)(base + r) * 16 + q] =
                    make_float4(p[0], p[1], p[2], p[3]);
            }
        }
        __syncthreads();
    }
}

// ---------------- fused edge pipeline (edge transformer + gate + scatter) ----
// smem floats: We1T[4352] We2T[4352] B[4352] bias[128] | src[64] dst[64]
#define EDGE_SMEM_BYTES ((3 * 4352 + 128) * 4 + 128 * 4)

__global__ void __launch_bounds__(256, 2)
edge_kernel(const float* __restrict__ ef,
            const int* __restrict__ src, const int* __restrict__ dst,
            const float* __restrict__ ec1, const float* __restrict__ ec2,
            int E)
{
    extern __shared__ float sm[];
    float* sW1 = sm;
    float* sW2 = sW1 + 4352;
    float* sB  = sW2 + 4352;
    float* sb  = sB + 4352;
    int*   sSrc = (int*)(sb + 128);
    int*   sDst = sSrc + 64;

    const int tid = threadIdx.x;
    for (int i = tid; i < 4352; i += 256) {
        sW1[i] = g_We1T[i];
        sW2[i] = g_We2T[i];
    }
    if (tid < 64) { sb[tid] = ec1[tid]; sb[64 + tid] = ec2[tid]; }
    __syncthreads();

    const int ntiles = (E + 63) >> 6;
    for (int t = blockIdx.x; t < ntiles; t += gridDim.x) {
        const int base = t << 6;
        const int valid = min(64, E - base);
        if (tid < 64) {
            int e = base + min(tid, valid - 1);
            sSrc[tid] = src[e];
            sDst[tid] = dst[e];
        }
        for (int idx = tid; idx < 1024; idx += 256) {
            int r = idx >> 4, q = idx & 15;
            float4 v = (r < valid)
                ? __ldg((const float4*)ef + (size_t)(base + r) * 16 + q)
                : make_float4(0.f, 0.f, 0.f, 0.f);
            float* p = sB + r * 68 + (q << 2);
            p[0] = v.x; p[1] = v.y; p[2] = v.z; p[3] = v.w;
        }
        __syncthreads();

        gemm_f2<64, 68, 68, 68>(sB, sW1, sb,      sB, tid);
        gemm_f2<64, 68, 68, 68>(sB, sW2, sb + 64, sB, tid);

        // gate with gathered per-node message + vector scatter-add
        for (int idx = tid; idx < 1024; idx += 256) {
            int r = idx >> 4, q = idx & 15;
            if (r < valid) {
                float4 m = __ldg((const float4*)g_msg + (size_t)sDst[r] * 16 + q);
                const float* pb = sB + r * 68 + (q << 2);
                float x0 = m.x * pb[0], x1 = m.y * pb[1];
                float x2 = m.z * pb[2], x3 = m.w * pb[3];
                float* addr = g_agg + (size_t)sSrc[r] * 64 + (q << 2);
                asm volatile("red.global.add.v4.f32 [%0], {%1,%2,%3,%4};"
                             :: "l"(addr), "f"(x0), "f"(x1), "f"(x2), "f"(x3)
                             : "memory");
            }
        }
        if (tid < valid) atomicAdd(&g_cnt[sSrc[tid]], 1.0f);
        __syncthreads();
    }
}

// ---------------- node update ----------------
// smem floats: Wu1T[8448] Wu2T[4352] A[64*132=8448] H[4352] bias[128]
#define NODE_SMEM_BYTES ((8448 + 4352 + 8448 + 4352 + 128) * 4)

__global__ void __launch_bounds__(256, 2)
node_kernel(const float* __restrict__ nf, float* __restrict__ out, int N)
{
    extern __shared__ float sm[];
    float* sW1 = sm;                 // 64 x 132 (WT)
    float* sW2 = sW1 + 8448;         // 64 x 68 (WT)
    float* sA  = sW2 + 4352;         // 64 x 132
    float* sH  = sA + 8448;          // 64 x 68
    float* sb  = sH + 4352;

    const int tid = threadIdx.x;
    for (int i = tid; i < 8448; i += 256) sW1[i] = g_Wu1T[i];
    for (int i = tid; i < 4352; i += 256) sW2[i] = g_Wu2T[i];
    if (tid < 64) { sb[tid] = g_cu1[tid]; sb[64 + tid] = g_cu2[tid]; }
    __syncthreads();

    const int ntiles = (N + 63) >> 6;
    for (int t = blockIdx.x; t < ntiles; t += gridDim.x) {
        const int base = t << 6;
        const int valid = min(64, N - base);
        // stage concat [node_feats | agg/max(cnt,1)] : 64 rows x 32 float4
        for (int idx = tid; idx < 2048; idx += 256) {
            int r = idx >> 5, q = idx & 31;
            float* p = sA + r * 132 + (q << 2);
            if (r < valid) {
                int n = base + r;
                if (q < 16) {
                    float4 v = __ldg((const float4*)nf + (size_t)n * 16 + q);
                    p[0] = v.x; p[1] = v.y; p[2] = v.z; p[3] = v.w;
                } else {
                    float inv = 1.0f / fmaxf(g_cnt[n], 1.0f);
                    float4 v = *((const float4*)g_agg + (size_t)n * 16 + (q - 16));
                    p[0] = v.x * inv; p[1] = v.y * inv;
                    p[2] = v.z * inv; p[3] = v.w * inv;
                }
            } else {
                p[0] = 0.f; p[1] = 0.f; p[2] = 0.f; p[3] = 0.f;
            }
        }
        __syncthreads();

        gemm_f2<128, 132, 132, 68>(sA, sW1, sb,      sH, tid);
        gemm_f2<64,  68,  68,  68>(sH, sW2, sb + 64, sH, tid);

        for (int idx = tid; idx < 1024; idx += 256) {
            int r = idx >> 4, q = idx & 15;
            if (r < valid) {
                const float* p = sH + r * 68 + (q << 2);
                ((float4*)out)[(size_t)(base + r) * 16 + q] =
                    make_float4(p[0], p[1], p[2], p[3]);
            }
        }
        __syncthreads();
    }
}

// ---------------- launch ----------------
extern "C" void kernel_launch(void* const* d_in, const int* in_sizes, int n_in,
                              void* d_out, int out_size)
{
    // Detect input ordering: dict order has src (size E~8e5) at index 2;
    // reference-signature order has m_g1 (size 64) at index 2.
    int pi;
    const int *src, *dst;
    int E;
    if (in_sizes[2] > 1000) {            // dict order: node, edge, src, dst, params...
        src = (const int*)d_in[2];
        dst = (const int*)d_in[3];
        E = in_sizes[2];
        pi = 4;
    } else {                              // reference order: params..., src, dst
        pi = 2;
        src = (const int*)d_in[30];
        dst = (const int*)d_in[31];
        E = in_sizes[30];
    }
    const float* nf = (const float*)d_in[0];
    const float* ef = (const float*)d_in[1];
    const int N = in_sizes[0] / 64;

    const float* P[28];
    for (int i = 0; i < 28; i++) P[i] = (const float*)d_in[pi + i];
    // P: 0..5 m1(g,b,mu,v,W,c) 6..11 m2 12..15 eW1,ec1,eW2,ec2 16..21 u1 22..27 u2

    cudaFuncSetAttribute(msg_kernel, cudaFuncAttributeMaxDynamicSharedMemorySize,
                         MSG_SMEM_BYTES);
    cudaFuncSetAttribute(edge_kernel, cudaFuncAttributeMaxDynamicSharedMemorySize,
                         EDGE_SMEM_BYTES);
    cudaFuncSetAttribute(node_kernel, cudaFuncAttributeMaxDynamicSharedMemorySize,
                         NODE_SMEM_BYTES);

    zero_kernel<<<512, 256>>>(N);
    prep_kernel<<<1, 256>>>(P[0], P[1], P[2], P[3], P[4], P[5],
                            P[6], P[7], P[8], P[9], P[10], P[11],
                            P[12], P[14],
                            P[16], P[17], P[18], P[19], P[20], P[21],
                            P[22], P[23], P[24], P[25], P[26], P[27]);
    msg_kernel<<<296, 256, MSG_SMEM_BYTES>>>(nf, N);
    edge_kernel<<<296, 256, EDGE_SMEM_BYTES>>>(ef, src, dst, P[13], P[15], E);
    node_kernel<<<296, 256, NODE_SMEM_BYTES>>>(nf, (float*)d_out, N);
}

// round 3
// speedup vs baseline: 1.5695x; 1.0662x over previous
#include <cuda_runtime.h>
#include <math.h>
#include <stdint.h>

#define EPS 1e-3f
#define NMAX 50048

typedef unsigned long long ull;

// ---------------- device scratch (static; no allocation) ----------------
__device__ float g_agg[NMAX * 64];   // segment sums [N,64]
__device__ float g_cnt[NMAX];        // segment counts
__device__ float g_msg[NMAX * 64];   // precomputed per-node message MLP output

// BN-folded / transposed weights (WT[c][k], row stride padded)
__device__ float g_Wm1T[64 * 68],  g_cm1[64];
__device__ float g_Wm2T[64 * 68],  g_cm2[64];
__device__ float g_We1T[64 * 68];
__device__ float g_We2T[64 * 68];
__device__ float g_Wu1T[64 * 132], g_cu1[64];
__device__ float g_Wu2T[64 * 68],  g_cu2[64];

// exact-to-1.5e-7 gelu via Abramowitz-Stegun 7.1.26 erf
__device__ __forceinline__ float gelu_f(float x) {
    float t = fabsf(x) * 0.70710678118654752440f;
    float s;
    asm("rcp.approx.f32 %0, %1;" : "=f"(s) : "f"(fmaf(0.3275911f, t, 1.0f)));
    float poly = fmaf(1.061405429f, s, -1.453152027f);
    poly = fmaf(poly, s, 1.421413741f);
    poly = fmaf(poly, s, -0.284496736f);
    poly = fmaf(poly, s, 0.254829592f);
    poly *= s;
    float h = 0.5f * poly * __expf(-t * t);   // 0.5*(1-erf(t))
    return x * ((x >= 0.0f) ? (1.0f - h) : h);
}

__device__ __forceinline__ void ffma2(ull& acc, ull a, ull b) {
    asm("fma.rn.f32x2 %0, %1, %2, %0;" : "+l"(acc) : "l"(a), "l"(b));
}

__device__ __forceinline__ float2 unpack_f2(ull v) {
    float2 r;
    asm("mov.b64 {%0, %1}, %2;" : "=f"(r.x), "=f"(r.y) : "l"(v));
    return r;
}

__device__ __forceinline__ uint32_t smaddr(const void* p) {
    return (uint32_t)__cvta_generic_to_shared(p);
}

__device__ __forceinline__ void cp16(void* smem_dst, const void* gsrc) {
    asm volatile("cp.async.cg.shared.global [%0], [%1], 16;"
                 :: "r"(smaddr(smem_dst)), "l"(gsrc));
}
__device__ __forceinline__ void cp4(void* smem_dst, const void* gsrc) {
    asm volatile("cp.async.ca.shared.global [%0], [%1], 4;"
                 :: "r"(smaddr(smem_dst)), "l"(gsrc));
}
__device__ __forceinline__ void cp_commit() {
    asm volatile("cp.async.commit_group;" ::: "memory");
}
__device__ __forceinline__ void cp_wait0() {
    asm volatile("cp.async.wait_group 0;" ::: "memory");
}

// ---------------- zero accumulators ----------------
__global__ void zero_kernel(int N) {
    int total = N * 64 + N;
    for (int i = blockIdx.x * blockDim.x + threadIdx.x; i < total;
         i += gridDim.x * blockDim.x) {
        if (i < N * 64) g_agg[i] = 0.0f;
        else            g_cnt[i - N * 64] = 0.0f;
    }
}

// ---------------- fold BN into weights, transpose all weights ----------------
__global__ void prep_kernel(
    const float* mg1, const float* mb1, const float* mm1, const float* mv1,
    const float* mW1, const float* mc1,
    const float* mg2, const float* mb2, const float* mm2, const float* mv2,
    const float* mW2, const float* mc2,
    const float* eW1, const float* eW2,
    const float* ug1, const float* ub1, const float* um1, const float* uv1,
    const float* uW1, const float* uc1,
    const float* ug2, const float* ub2, const float* um2, const float* uv2,
    const float* uW2, const float* uc2)
{
    int tid = threadIdx.x;  // 256 threads, 1 block
    for (int idx = tid; idx < 64 * 64; idx += 256) {
        int c = idx >> 6, k = idx & 63;
        g_Wm1T[c * 68 + k] = mg1[k] * rsqrtf(mv1[k] + EPS) * mW1[k * 64 + c];
        g_Wm2T[c * 68 + k] = mg2[k] * rsqrtf(mv2[k] + EPS) * mW2[k * 64 + c];
        g_Wu2T[c * 68 + k] = ug2[k] * rsqrtf(uv2[k] + EPS) * uW2[k * 64 + c];
        g_We1T[c * 68 + k] = eW1[k * 64 + c];
        g_We2T[c * 68 + k] = eW2[k * 64 + c];
    }
    for (int idx = tid; idx < 64 * 128; idx += 256) {
        int c = idx >> 7, k = idx & 127;
        g_Wu1T[c * 132 + k] = ug1[k] * rsqrtf(uv1[k] + EPS) * uW1[k * 64 + c];
    }
    if (tid < 64) {
        float s1 = 0.f, s2 = 0.f, s4 = 0.f;
        for (int k = 0; k < 64; k++) {
            float sc;
            sc = mg1[k] * rsqrtf(mv1[k] + EPS);
            s1 += (mb1[k] - mm1[k] * sc) * mW1[k * 64 + tid];
            sc = mg2[k] * rsqrtf(mv2[k] + EPS);
            s2 += (mb2[k] - mm2[k] * sc) * mW2[k * 64 + tid];
            sc = ug2[k] * rsqrtf(uv2[k] + EPS);
            s4 += (ub2[k] - um2[k] * sc) * uW2[k * 64 + tid];
        }
        float s3 = 0.f;
        for (int k = 0; k < 128; k++) {
            float sc = ug1[k] * rsqrtf(uv1[k] + EPS);
            s3 += (ub1[k] - um1[k] * sc) * uW1[k * 64 + tid];
        }
        g_cm1[tid] = mc1[tid] + s1;
        g_cm2[tid] = mc2[tid] + s2;
        g_cu1[tid] = uc1[tid] + s3;
        g_cu2[tid] = uc2[tid] + s4;
    }
}

// ---------------- FFMA2 tile GEMM (template; used by msg/node kernels) ------
// thread (rg = tid&15) rows rg+16i; cols c0=4*(tid>>4) .. +3 (consecutive)
template <int K, int LDA, int LDW, int LDO>
__device__ __forceinline__ void gemm_f2(const float* __restrict__ A,
                                        const float* __restrict__ WT,
                                        const float* __restrict__ bias,
                                        float* __restrict__ out, int tid)
{
    const int rg = tid & 15, c0 = (tid >> 4) << 2;
    ull acc[4][4];
#pragma unroll
    for (int i = 0; i < 4; i++)
#pragma unroll
        for (int j = 0; j < 4; j++) acc[i][j] = 0ull;

#pragma unroll 4
    for (int k = 0; k < K; k += 4) {
        ulonglong2 a[4], w[4];
#pragma unroll
        for (int i = 0; i < 4; i++)
            a[i] = *(const ulonglong2*)(A + (rg + 16 * i) * LDA + k);
#pragma unroll
        for (int j = 0; j < 4; j++)
            w[j] = *(const ulonglong2*)(WT + (c0 + j) * LDW + k);
#pragma unroll
        for (int i = 0; i < 4; i++)
#pragma unroll
            for (int j = 0; j < 4; j++) {
                ffma2(acc[i][j], a[i].x, w[j].x);
                ffma2(acc[i][j], a[i].y, w[j].y);
            }
    }
    __syncthreads();
#pragma unroll
    for (int i = 0; i < 4; i++) {
        float v[4];
#pragma unroll
        for (int j = 0; j < 4; j++) {
            float2 p = unpack_f2(acc[i][j]);
            v[j] = gelu_f(p.x + p.y + bias[c0 + j]);
        }
        *(float4*)(out + (rg + 16 * i) * LDO + c0) =
            make_float4(v[0], v[1], v[2], v[3]);
    }
    __syncthreads();
}

// ---------------- per-node message MLP precompute ----------------
#define MSG_SMEM_BYTES ((3 * 4352 + 128) * 4)

__global__ void __launch_bounds__(256, 2)
msg_kernel(const float* __restrict__ nf, int N)
{
    extern __shared__ float sm[];
    float* sW1 = sm;
    float* sW2 = sW1 + 4352;
    float* sA  = sW2 + 4352;
    float* sb  = sA + 4352;

    const int tid = threadIdx.x;
    for (int i = tid; i < 4352; i += 256) {
        sW1[i] = g_Wm1T[i];
        sW2[i] = g_Wm2T[i];
    }
    if (tid < 64) { sb[tid] = g_cm1[tid]; sb[64 + tid] = g_cm2[tid]; }
    __syncthreads();

    const int ntiles = (N + 63) >> 6;
    for (int t = blockIdx.x; t < ntiles; t += gridDim.x) {
        const int base = t << 6;
        const int valid = min(64, N - base);
        for (int idx = tid; idx < 1024; idx += 256) {
            int r = idx >> 4, q = idx & 15;
            float4 v = (r < valid)
                ? __ldg((const float4*)nf + (size_t)(base + r) * 16 + q)
                : make_float4(0.f, 0.f, 0.f, 0.f);
            float* p = sA + r * 68 + (q << 2);
            p[0] = v.x; p[1] = v.y; p[2] = v.z; p[3] = v.w;
        }
        __syncthreads();

        gemm_f2<64, 68, 68, 68>(sA, sW1, sb,      sA, tid);
        gemm_f2<64, 68, 68, 68>(sA, sW2, sb + 64, sA, tid);

        for (int idx = tid; idx < 1024; idx += 256) {
            int r = idx >> 4, q = idx & 15;
            if (r < valid) {
                const float* p = sA + r * 68 + (q << 2);
                ((float4*)g_msg)[(size_t)(base + r) * 16 + q] =
                    make_float4(p[0], p[1], p[2], p[3]);
            }
        }
        __syncthreads();
    }
}

// ---------------- pipelined fused edge kernel ----------------
// smem floats: We1T[4352] We2T[4352] sB[4352] buf0[4352] buf1[4352] bias[128]
//              + src[2][64], dst[2][64] ints
#define EDGE_SMEM_BYTES ((5 * 4352 + 128) * 4 + 256 * 4)

__global__ void __launch_bounds__(256, 2)
edge_kernel(const float* __restrict__ ef,
            const int* __restrict__ src, const int* __restrict__ dst,
            const float* __restrict__ ec1, const float* __restrict__ ec2,
            int E)
{
    extern __shared__ float sm[];
    float* sW1  = sm;
    float* sW2  = sW1 + 4352;
    float* sB   = sW2 + 4352;
    float* buf0 = sB + 4352;
    float* buf1 = buf0 + 4352;
    float* sb   = buf1 + 4352;
    int*   sSrc = (int*)(sb + 128);   // [2][64]
    int*   sDst = sSrc + 128;         // [2][64]

    const int tid = threadIdx.x;
    const int rg = tid & 15, c0 = (tid >> 4) << 2;

    for (int i = tid; i < 4352; i += 256) {
        sW1[i] = g_We1T[i];
        sW2[i] = g_We2T[i];
    }
    if (tid < 64) { sb[tid] = ec1[tid]; sb[64 + tid] = ec2[tid]; }

    const int ntiles = (E + 63) >> 6;
    int t = blockIdx.x;
    int p = 0;

    // prologue: stage first tile into buf0 / slot 0
    if (t < ntiles) {
        const int base = t << 6;
        const int valid = min(64, E - base);
        for (int idx = tid; idx < 1024; idx += 256) {
            int r = idx >> 4, q = idx & 15;
            if (r < valid)
                cp16(buf0 + r * 68 + (q << 2), ef + (size_t)(base + r) * 64 + (q << 2));
        }
        if (tid < 64) {
            if (tid < valid) {
                cp4(sSrc + tid, src + base + tid);
                cp4(sDst + tid, dst + base + tid);
            } else { sSrc[tid] = 0; sDst[tid] = 0; }
        }
    }
    cp_commit();
    cp_wait0();
    __syncthreads();

    float4 b1v = *(const float4*)(sb + c0);
    float4 b2v = *(const float4*)(sb + 64 + c0);

    for (; t < ntiles; t += gridDim.x) {
        const int base = t << 6;
        const int valid = min(64, E - base);
        float* bufA = p ? buf1 : buf0;
        float* bufN = p ? buf0 : buf1;
        int* curS = sSrc + p * 64;
        int* curD = sDst + p * 64;

        // phase 0: gather per-node messages for this thread's outputs into regs
        float4 mreg[4];
#pragma unroll
        for (int i = 0; i < 4; i++) {
            int d = curD[rg + 16 * i];
            mreg[i] = __ldg((const float4*)g_msg + (size_t)d * 16 + (c0 >> 2));
        }

        // prefetch next tile
        int tn = t + gridDim.x;
        if (tn < ntiles) {
            const int basen = tn << 6;
            const int validn = min(64, E - basen);
            int* nS = sSrc + (p ^ 1) * 64;
            int* nD = sDst + (p ^ 1) * 64;
            for (int idx = tid; idx < 1024; idx += 256) {
                int r = idx >> 4, q = idx & 15;
                if (r < validn)
                    cp16(bufN + r * 68 + (q << 2),
                         ef + (size_t)(basen + r) * 64 + (q << 2));
            }
            if (tid < 64) {
                if (tid < validn) {
                    cp4(nS + tid, src + basen + tid);
                    cp4(nD + tid, dst + basen + tid);
                } else { nS[tid] = 0; nD[tid] = 0; }
            }
        }
        cp_commit();

        // GEMM1: bufA @ W1 -> gelu -> sB
        {
            ull acc[4][4];
#pragma unroll
            for (int i = 0; i < 4; i++)
#pragma unroll
                for (int j = 0; j < 4; j++) acc[i][j] = 0ull;
#pragma unroll 4
            for (int k = 0; k < 64; k += 4) {
                ulonglong2 a[4], w[4];
#pragma unroll
                for (int i = 0; i < 4; i++)
                    a[i] = *(const ulonglong2*)(bufA + (rg + 16 * i) * 68 + k);
#pragma unroll
                for (int j = 0; j < 4; j++)
                    w[j] = *(const ulonglong2*)(sW1 + (c0 + j) * 68 + k);
#pragma unroll
                for (int i = 0; i < 4; i++)
#pragma unroll
                    for (int j = 0; j < 4; j++) {
                        ffma2(acc[i][j], a[i].x, w[j].x);
                        ffma2(acc[i][j], a[i].y, w[j].y);
                    }
            }
#pragma unroll
            for (int i = 0; i < 4; i++) {
                float2 q0 = unpack_f2(acc[i][0]);
                float2 q1 = unpack_f2(acc[i][1]);
                float2 q2 = unpack_f2(acc[i][2]);
                float2 q3 = unpack_f2(acc[i][3]);
                *(float4*)(sB + (rg + 16 * i) * 68 + c0) = make_float4(
                    gelu_f(q0.x + q0.y + b1v.x), gelu_f(q1.x + q1.y + b1v.y),
                    gelu_f(q2.x + q2.y + b1v.z), gelu_f(q3.x + q3.y + b1v.w));
            }
        }
        __syncthreads();

        // GEMM2: sB @ W2 -> acc; epilogue gates with mreg and scatters
        {
            ull acc[4][4];
#pragma unroll
            for (int i = 0; i < 4; i++)
#pragma unroll
                for (int j = 0; j < 4; j++) acc[i][j] = 0ull;
#pragma unroll 4
            for (int k = 0; k < 64; k += 4) {
                ulonglong2 a[4], w[4];
#pragma unroll
                for (int i = 0; i < 4; i++)
                    a[i] = *(const ulonglong2*)(sB + (rg + 16 * i) * 68 + k);
#pragma unroll
                for (int j = 0; j < 4; j++)
                    w[j] = *(const ulonglong2*)(sW2 + (c0 + j) * 68 + k);
#pragma unroll
                for (int i = 0; i < 4; i++)
#pragma unroll
                    for (int j = 0; j < 4; j++) {
                        ffma2(acc[i][j], a[i].x, w[j].x);
                        ffma2(acc[i][j], a[i].y, w[j].y);
                    }
            }
            cp_wait0();
            __syncthreads();   // sB reads done; next tile's buffers visible

#pragma unroll
            for (int i = 0; i < 4; i++) {
                int row = rg + 16 * i;
                float2 q0 = unpack_f2(acc[i][0]);
                float2 q1 = unpack_f2(acc[i][1]);
                float2 q2 = unpack_f2(acc[i][2]);
                float2 q3 = unpack_f2(acc[i][3]);
                float x0 = gelu_f(q0.x + q0.y + b2v.x) * mreg[i].x;
                float x1 = gelu_f(q1.x + q1.y + b2v.y) * mreg[i].y;
                float x2 = gelu_f(q2.x + q2.y + b2v.z) * mreg[i].z;
                float x3 = gelu_f(q3.x + q3.y + b2v.w) * mreg[i].w;
                if (row < valid) {
                    float* addr = g_agg + (size_t)curS[row] * 64 + c0;
                    asm volatile("red.global.add.v4.f32 [%0], {%1,%2,%3,%4};"
                                 :: "l"(addr), "f"(x0), "f"(x1), "f"(x2), "f"(x3)
                                 : "memory");
                }
            }
            if (tid < valid) atomicAdd(&g_cnt[curS[tid]], 1.0f);
        }
        p ^= 1;
    }
}

// ---------------- node update ----------------
#define NODE_SMEM_BYTES ((8448 + 4352 + 8448 + 4352 + 128) * 4)

__global__ void __launch_bounds__(256, 2)
node_kernel(const float* __restrict__ nf, float* __restrict__ out, int N)
{
    extern __shared__ float sm[];
    float* sW1 = sm;                 // 64 x 132 (WT)
    float* sW2 = sW1 + 8448;         // 64 x 68 (WT)
    float* sA  = sW2 + 4352;         // 64 x 132
    float* sH  = sA + 8448;          // 64 x 68
    float* sb  = sH + 4352;

    const int tid = threadIdx.x;
    for (int i = tid; i < 8448; i += 256) sW1[i] = g_Wu1T[i];
    for (int i = tid; i < 4352; i += 256) sW2[i] = g_Wu2T[i];
    if (tid < 64) { sb[tid] = g_cu1[tid]; sb[64 + tid] = g_cu2[tid]; }
    __syncthreads();

    const int ntiles = (N + 63) >> 6;
    for (int t = blockIdx.x; t < ntiles; t += gridDim.x) {
        const int base = t << 6;
        const int valid = min(64, N - base);
        for (int idx = tid; idx < 2048; idx += 256) {
            int r = idx >> 5, q = idx & 31;
            float* p = sA + r * 132 + (q << 2);
            if (r < valid) {
                int n = base + r;
                if (q < 16) {
                    float4 v = __ldg((const float4*)nf + (size_t)n * 16 + q);
                    p[0] = v.x; p[1] = v.y; p[2] = v.z; p[3] = v.w;
                } else {
                    float inv = 1.0f / fmaxf(g_cnt[n], 1.0f);
                    float4 v = *((const float4*)g_agg + (size_t)n * 16 + (q - 16));
                    p[0] = v.x * inv; p[1] = v.y * inv;
                    p[2] = v.z * inv; p[3] = v.w * inv;
                }
            } else {
                p[0] = 0.f; p[1] = 0.f; p[2] = 0.f; p[3] = 0.f;
            }
        }
        __syncthreads();

        gemm_f2<128, 132, 132, 68>(sA, sW1, sb,      sH, tid);
        gemm_f2<64,  68,  68,  68>(sH, sW2, sb + 64, sH, tid);

        for (int idx = tid; idx < 1024; idx += 256) {
            int r = idx >> 4, q = idx & 15;
            if (r < valid) {
                const float* p = sH + r * 68 + (q << 2);
                ((float4*)out)[(size_t)(base + r) * 16 + q] =
                    make_float4(p[0], p[1], p[2], p[3]);
            }
        }
        __syncthreads();
    }
}

// ---------------- launch ----------------
extern "C" void kernel_launch(void* const* d_in, const int* in_sizes, int n_in,
                              void* d_out, int out_size)
{
    int pi;
    const int *src, *dst;
    int E;
    if (in_sizes[2] > 1000) {            // dict order: node, edge, src, dst, params...
        src = (const int*)d_in[2];
        dst = (const int*)d_in[3];
        E = in_sizes[2];
        pi = 4;
    } else {                              // reference order: params..., src, dst
        pi = 2;
        src = (const int*)d_in[30];
        dst = (const int*)d_in[31];
        E = in_sizes[30];
    }
    const float* nf = (const float*)d_in[0];
    const float* ef = (const float*)d_in[1];
    const int N = in_sizes[0] / 64;

    const float* P[28];
    for (int i = 0; i < 28; i++) P[i] = (const float*)d_in[pi + i];
    // P: 0..5 m1(g,b,mu,v,W,c) 6..11 m2 12..15 eW1,ec1,eW2,ec2 16..21 u1 22..27 u2

    cudaFuncSetAttribute(msg_kernel, cudaFuncAttributeMaxDynamicSharedMemorySize,
                         MSG_SMEM_BYTES);
    cudaFuncSetAttribute(edge_kernel, cudaFuncAttributeMaxDynamicSharedMemorySize,
                         EDGE_SMEM_BYTES);
    cudaFuncSetAttribute(node_kernel, cudaFuncAttributeMaxDynamicSharedMemorySize,
                         NODE_SMEM_BYTES);

    zero_kernel<<<512, 256>>>(N);
    prep_kernel<<<1, 256>>>(P[0], P[1], P[2], P[3], P[4], P[5],
                            P[6], P[7], P[8], P[9], P[10], P[11],
                            P[12], P[14],
                            P[16], P[17], P[18], P[19], P[20], P[21],
                            P[22], P[23], P[24], P[25], P[26], P[27]);
    msg_kernel<<<296, 256, MSG_SMEM_BYTES>>>(nf, N);
    edge_kernel<<<296, 256, EDGE_SMEM_BYTES>>>(ef, src, dst, P[13], P[15], E);
    node_kernel<<<296, 256, NODE_SMEM_BYTES>>>(nf, (float*)d_out, N);
}

// round 7
// speedup vs baseline: 1.5873x; 1.0113x over previous
#include <cuda_runtime.h>
#include <math.h>
#include <stdint.h>

#define EPS 1e-3f
#define NMAX 50048

typedef unsigned long long ull;

// ---------------- device scratch (static; no allocation) ----------------
__device__ float g_agg[NMAX * 64];   // segment sums [N,64]
__device__ float g_cnt[NMAX];        // segment counts
__device__ float g_msg[NMAX * 64];   // precomputed per-node message MLP output

// BN-folded / transposed weights (WT[c][k], row stride padded)
__device__ float g_Wm1T[64 * 68],  g_cm1[64];
__device__ float g_Wm2T[64 * 68],  g_cm2[64];
__device__ float g_We1T[64 * 68];
__device__ float g_We2T[64 * 68];
__device__ float g_Wu1T[64 * 132], g_cu1[64];
__device__ float g_Wu2T[64 * 68],  g_cu2[64];

// gelu via Abramowitz-Stegun 7.1.28 erf (|abs err| ~3e-7): NO expf —
// 1 MUFU (rcp) + ~12 FMA. p^-16 via rcp + 4 squarings; saturates gracefully.
__device__ __forceinline__ float gelu_f(float x) {
    float t = fabsf(x) * 0.70710678118654752440f;
    float p = fmaf(0.0000430638f, t, 0.0002765672f);
    p = fmaf(p, t, 0.0001520143f);
    p = fmaf(p, t, 0.0092705272f);
    p = fmaf(p, t, 0.0422820123f);
    p = fmaf(p, t, 0.0705230784f);
    p = fmaf(p, t, 1.0f);
    float r;
    asm("rcp.approx.f32 %0, %1;" : "=f"(r) : "f"(p));
    r = r * r;  r = r * r;  r = r * r;  r = r * r;   // p^-16
    float h = 0.5f * r;                              // 0.5*(1-erf(t))
    return x * ((x >= 0.0f) ? (1.0f - h) : h);
}

__device__ __forceinline__ void ffma2(ull& acc, ull a, ull b) {
    asm("fma.rn.f32x2 %0, %1, %2, %0;" : "+l"(acc) : "l"(a), "l"(b));
}

__device__ __forceinline__ float2 unpack_f2(ull v) {
    float2 r;
    asm("mov.b64 {%0, %1}, %2;" : "=f"(r.x), "=f"(r.y) : "l"(v));
    return r;
}

__device__ __forceinline__ uint32_t smaddr(const void* p) {
    return (uint32_t)__cvta_generic_to_shared(p);
}

__device__ __forceinline__ void cp16(void* smem_dst, const void* gsrc) {
    asm volatile("cp.async.cg.shared.global [%0], [%1], 16;"
                 :: "r"(smaddr(smem_dst)), "l"(gsrc));
}
__device__ __forceinline__ void cp4(void* smem_dst, const void* gsrc) {
    asm volatile("cp.async.ca.shared.global [%0], [%1], 4;"
                 :: "r"(smaddr(smem_dst)), "l"(gsrc));
}
__device__ __forceinline__ void cp_commit() {
    asm volatile("cp.async.commit_group;" ::: "memory");
}
__device__ __forceinline__ void cp_wait0() {
    asm volatile("cp.async.wait_group 0;" ::: "memory");
}

// ---------------- zero accumulators ----------------
__global__ void zero_kernel(int N) {
    int total = N * 64 + N;
    for (int i = blockIdx.x * blockDim.x + threadIdx.x; i < total;
         i += gridDim.x * blockDim.x) {
        if (i < N * 64) g_agg[i] = 0.0f;
        else            g_cnt[i - N * 64] = 0.0f;
    }
}

// ---------------- fold BN into weights, transpose all weights ----------------
__global__ void prep_kernel(
    const float* mg1, const float* mb1, const float* mm1, const float* mv1,
    const float* mW1, const float* mc1,
    const float* mg2, const float* mb2, const float* mm2, const float* mv2,
    const float* mW2, const float* mc2,
    const float* eW1, const float* eW2,
    const float* ug1, const float* ub1, const float* um1, const float* uv1,
    const float* uW1, const float* uc1,
    const float* ug2, const float* ub2, const float* um2, const float* uv2,
    const float* uW2, const float* uc2)
{
    int tid = threadIdx.x;  // 256 threads, 1 block
    for (int idx = tid; idx < 64 * 64; idx += 256) {
        int c = idx >> 6, k = idx & 63;
        g_Wm1T[c * 68 + k] = mg1[k] * rsqrtf(mv1[k] + EPS) * mW1[k * 64 + c];
        g_Wm2T[c * 68 + k] = mg2[k] * rsqrtf(mv2[k] + EPS) * mW2[k * 64 + c];
        g_Wu2T[c * 68 + k] = ug2[k] * rsqrtf(uv2[k] + EPS) * uW2[k * 64 + c];
        g_We1T[c * 68 + k] = eW1[k * 64 + c];
        g_We2T[c * 68 + k] = eW2[k * 64 + c];
    }
    for (int idx = tid; idx < 64 * 128; idx += 256) {
        int c = idx >> 7, k = idx & 127;
        g_Wu1T[c * 132 + k] = ug1[k] * rsqrtf(uv1[k] + EPS) * uW1[k * 64 + c];
    }
    if (tid < 64) {
        float s1 = 0.f, s2 = 0.f, s4 = 0.f;
        for (int k = 0; k < 64; k++) {
            float sc;
            sc = mg1[k] * rsqrtf(mv1[k] + EPS);
            s1 += (mb1[k] - mm1[k] * sc) * mW1[k * 64 + tid];
            sc = mg2[k] * rsqrtf(mv2[k] + EPS);
            s2 += (mb2[k] - mm2[k] * sc) * mW2[k * 64 + tid];
            sc = ug2[k] * rsqrtf(uv2[k] + EPS);
            s4 += (ub2[k] - um2[k] * sc) * uW2[k * 64 + tid];
        }
        float s3 = 0.f;
        for (int k = 0; k < 128; k++) {
            float sc = ug1[k] * rsqrtf(uv1[k] + EPS);
            s3 += (ub1[k] - um1[k] * sc) * uW1[k * 64 + tid];
        }
        g_cm1[tid] = mc1[tid] + s1;
        g_cm2[tid] = mc2[tid] + s2;
        g_cu1[tid] = uc1[tid] + s3;
        g_cu2[tid] = uc2[tid] + s4;
    }
}

// ---------------- FFMA2 tile GEMM (template; used by msg/node kernels) ------
template <int K, int LDA, int LDW, int LDO>
__device__ __forceinline__ void gemm_f2(const float* __restrict__ A,
                                        const float* __restrict__ WT,
                                        const float* __restrict__ bias,
                                        float* __restrict__ out, int tid)
{
    const int rg = tid & 15, c0 = (tid >> 4) << 2;
    ull acc[4][4];
#pragma unroll
    for (int i = 0; i < 4; i++)
#pragma unroll
        for (int j = 0; j < 4; j++) acc[i][j] = 0ull;

#pragma unroll 4
    for (int k = 0; k < K; k += 4) {
        ulonglong2 a[4], w[4];
#pragma unroll
        for (int i = 0; i < 4; i++)
            a[i] = *(const ulonglong2*)(A + (rg + 16 * i) * LDA + k);
#pragma unroll
        for (int j = 0; j < 4; j++)
            w[j] = *(const ulonglong2*)(WT + (c0 + j) * LDW + k);
#pragma unroll
        for (int i = 0; i < 4; i++)
#pragma unroll
            for (int j = 0; j < 4; j++) {
                ffma2(acc[i][j], a[i].x, w[j].x);
                ffma2(acc[i][j], a[i].y, w[j].y);
            }
    }
    __syncthreads();
#pragma unroll
    for (int i = 0; i < 4; i++) {
        float v[4];
#pragma unroll
        for (int j = 0; j < 4; j++) {
            float2 p = unpack_f2(acc[i][j]);
            v[j] = gelu_f(p.x + p.y + bias[c0 + j]);
        }
        *(float4*)(out + (rg + 16 * i) * LDO + c0) =
            make_float4(v[0], v[1], v[2], v[3]);
    }
    __syncthreads();
}

// ---------------- per-node message MLP precompute ----------------
#define MSG_SMEM_BYTES ((3 * 4352 + 128) * 4)

__global__ void __launch_bounds__(256, 2)
msg_kernel(const float* __restrict__ nf, int N)
{
    extern __shared__ float sm[];
    float* sW1 = sm;
    float* sW2 = sW1 + 4352;
    float* sA  = sW2 + 4352;
    float* sb  = sA + 4352;

    const int tid = threadIdx.x;
    for (int i = tid; i < 4352; i += 256) {
        sW1[i] = g_Wm1T[i];
        sW2[i] = g_Wm2T[i];
    }
    if (tid < 64) { sb[tid] = g_cm1[tid]; sb[64 + tid] = g_cm2[tid]; }
    __syncthreads();

    const int ntiles = (N + 63) >> 6;
    for (int t = blockIdx.x; t < ntiles; t += gridDim.x) {
        const int base = t << 6;
        const int valid = min(64, N - base);
        for (int idx = tid; idx < 1024; idx += 256) {
            int r = idx >> 4, q = idx & 15;
            float4 v = (r < valid)
                ? __ldg((const float4*)nf + (size_t)(base + r) * 16 + q)
                : make_float4(0.f, 0.f, 0.f, 0.f);
            float* p = sA + r * 68 + (q << 2);
            p[0] = v.x; p[1] = v.y; p[2] = v.z; p[3] = v.w;
        }
        __syncthreads();

        gemm_f2<64, 68, 68, 68>(sA, sW1, sb,      sA, tid);
        gemm_f2<64, 68, 68, 68>(sA, sW2, sb + 64, sA, tid);

        for (int idx = tid; idx < 1024; idx += 256) {
            int r = idx >> 4, q = idx & 15;
            if (r < valid) {
                const float* p = sA + r * 68 + (q << 2);
                ((float4*)g_msg)[(size_t)(base + r) * 16 + q] =
                    make_float4(p[0], p[1], p[2], p[3]);
            }
        }
        __syncthreads();
    }
}

// ---------------- pipelined fused edge kernel ----------------
#define EDGE_SMEM_BYTES ((5 * 4352 + 128) * 4 + 256 * 4)

__global__ void __launch_bounds__(256, 2)
edge_kernel(const float* __restrict__ ef,
            const int* __restrict__ src, const int* __restrict__ dst,
            const float* __restrict__ ec1, const float* __restrict__ ec2,
            int E)
{
    extern __shared__ float sm[];
    float* sW1  = sm;
    float* sW2  = sW1 + 4352;
    float* sB   = sW2 + 4352;
    float* buf0 = sB + 4352;
    float* buf1 = buf0 + 4352;
    float* sb   = buf1 + 4352;
    int*   sSrc = (int*)(sb + 128);   // [2][64]
    int*   sDst = sSrc + 128;         // [2][64]

    const int tid = threadIdx.x;
    const int rg = tid & 15, c0 = (tid >> 4) << 2;

    for (int i = tid; i < 4352; i += 256) {
        sW1[i] = g_We1T[i];
        sW2[i] = g_We2T[i];
    }
    if (tid < 64) { sb[tid] = ec1[tid]; sb[64 + tid] = ec2[tid]; }

    const int ntiles = (E + 63) >> 6;
    int t = blockIdx.x;
    int p = 0;

    if (t < ntiles) {
        const int base = t << 6;
        const int valid = min(64, E - base);
        for (int idx = tid; idx < 1024; idx += 256) {
            int r = idx >> 4, q = idx & 15;
            if (r < valid)
                cp16(buf0 + r * 68 + (q << 2), ef + (size_t)(base + r) * 64 + (q << 2));
        }
        if (tid < 64) {
            if (tid < valid) {
                cp4(sSrc + tid, src + base + tid);
                cp4(sDst + tid, dst + base + tid);
            } else { sSrc[tid] = 0; sDst[tid] = 0; }
        }
    }
    cp_commit();
    cp_wait0();
    __syncthreads();

    float4 b1v = *(const float4*)(sb + c0);
    float4 b2v = *(const float4*)(sb + 64 + c0);

    for (; t < ntiles; t += gridDim.x) {
        const int base = t << 6;
        const int valid = min(64, E - base);
        float* bufA = p ? buf1 : buf0;
        float* bufN = p ? buf0 : buf1;
        int* curS = sSrc + p * 64;
        int* curD = sDst + p * 64;

        float4 mreg[4];
#pragma unroll
        for (int i = 0; i < 4; i++) {
            int d = curD[rg + 16 * i];
            mreg[i] = __ldg((const float4*)g_msg + (size_t)d * 16 + (c0 >> 2));
        }

        int tn = t + gridDim.x;
        if (tn < ntiles) {
            const int basen = tn << 6;
            const int validn = min(64, E - basen);
            int* nS = sSrc + (p ^ 1) * 64;
            int* nD = sDst + (p ^ 1) * 64;
            for (int idx = tid; idx < 1024; idx += 256) {
                int r = idx >> 4, q = idx & 15;
                if (r < validn)
                    cp16(bufN + r * 68 + (q << 2),
                         ef + (size_t)(basen + r) * 64 + (q << 2));
            }
            if (tid < 64) {
                if (tid < validn) {
                    cp4(nS + tid, src + basen + tid);
                    cp4(nD + tid, dst + basen + tid);
                } else { nS[tid] = 0; nD[tid] = 0; }
            }
        }
        cp_commit();

        // GEMM1: bufA @ W1 -> gelu -> sB
        {
            ull acc[4][4];
#pragma unroll
            for (int i = 0; i < 4; i++)
#pragma unroll
                for (int j = 0; j < 4; j++) acc[i][j] = 0ull;
#pragma unroll 4
            for (int k = 0; k < 64; k += 4) {
                ulonglong2 a[4], w[4];
#pragma unroll
                for (int i = 0; i < 4; i++)
                    a[i] = *(const ulonglong2*)(bufA + (rg + 16 * i) * 68 + k);
#pragma unroll
                for (int j = 0; j < 4; j++)
                    w[j] = *(const ulonglong2*)(sW1 + (c0 + j) * 68 + k);
#pragma unroll
                for (int i = 0; i < 4; i++)
#pragma unroll
                    for (int j = 0; j < 4; j++) {
                        ffma2(acc[i][j], a[i].x, w[j].x);
                        ffma2(acc[i][j], a[i].y, w[j].y);
                    }
            }
#pragma unroll
            for (int i = 0; i < 4; i++) {
                float2 q0 = unpack_f2(acc[i][0]);
                float2 q1 = unpack_f2(acc[i][1]);
                float2 q2 = unpack_f2(acc[i][2]);
                float2 q3 = unpack_f2(acc[i][3]);
                *(float4*)(sB + (rg + 16 * i) * 68 + c0) = make_float4(
                    gelu_f(q0.x + q0.y + b1v.x), gelu_f(q1.x + q1.y + b1v.y),
                    gelu_f(q2.x + q2.y + b1v.z), gelu_f(q3.x + q3.y + b1v.w));
            }
        }
        __syncthreads();

        // GEMM2: sB @ W2 -> gate with mreg -> scatter
        {
            ull acc[4][4];
#pragma unroll
            for (int i = 0; i < 4; i++)
#pragma unroll
                for (int j = 0; j < 4; j++) acc[i][j] = 0ull;
#pragma unroll 4
            for (int k = 0; k < 64; k += 4) {
                ulonglong2 a[4], w[4];
#pragma unroll
                for (int i = 0; i < 4; i++)
                    a[i] = *(const ulonglong2*)(sB + (rg + 16 * i) * 68 + k);
#pragma unroll
                for (int j = 0; j < 4; j++)
                    w[j] = *(const ulonglong2*)(sW2 + (c0 + j) * 68 + k);
#pragma unroll
                for (int i = 0; i < 4; i++)
#pragma unroll
                    for (int j = 0; j < 4; j++) {
                        ffma2(acc[i][j], a[i].x, w[j].x);
                        ffma2(acc[i][j], a[i].y, w[j].y);
                    }
            }
            cp_wait0();
            __syncthreads();

#pragma unroll
            for (int i = 0; i < 4; i++) {
                int row = rg + 16 * i;
                float2 q0 = unpack_f2(acc[i][0]);
                float2 q1 = unpack_f2(acc[i][1]);
                float2 q2 = unpack_f2(acc[i][2]);
                float2 q3 = unpack_f2(acc[i][3]);
                float x0 = gelu_f(q0.x + q0.y + b2v.x) * mreg[i].x;
                float x1 = gelu_f(q1.x + q1.y + b2v.y) * mreg[i].y;
                float x2 = gelu_f(q2.x + q2.y + b2v.z) * mreg[i].z;
                float x3 = gelu_f(q3.x + q3.y + b2v.w) * mreg[i].w;
                if (row < valid) {
                    float* addr = g_agg + (size_t)curS[row] * 64 + c0;
                    asm volatile("red.global.add.v4.f32 [%0], {%1,%2,%3,%4};"
                                 :: "l"(addr), "f"(x0), "f"(x1), "f"(x2), "f"(x3)
                                 : "memory");
                }
            }
            if (tid < valid) atomicAdd(&g_cnt[curS[tid]], 1.0f);
        }
        p ^= 1;
    }
}

// ---------------- node update ----------------
#define NODE_SMEM_BYTES ((8448 + 4352 + 8448 + 4352 + 128) * 4)

__global__ void __launch_bounds__(256, 2)
node_kernel(const float* __restrict__ nf, float* __restrict__ out, int N)
{
    extern __shared__ float sm[];
    float* sW1 = sm;                 // 64 x 132 (WT)
    float* sW2 = sW1 + 8448;         // 64 x 68 (WT)
    float* sA  = sW2 + 4352;         // 64 x 132
    float* sH  = sA + 8448;          // 64 x 68
    float* sb  = sH + 4352;

    const int tid = threadIdx.x;
    for (int i = tid; i < 8448; i += 256) sW1[i] = g_Wu1T[i];
    for (int i = tid; i < 4352; i += 256) sW2[i] = g_Wu2T[i];
    if (tid < 64) { sb[tid] = g_cu1[tid]; sb[64 + tid] = g_cu2[tid]; }
    __syncthreads();

    const int ntiles = (N + 63) >> 6;
    for (int t = blockIdx.x; t < ntiles; t += gridDim.x) {
        const int base = t << 6;
        const int valid = min(64, N - base);
        for (int idx = tid; idx < 2048; idx += 256) {
            int r = idx >> 5, q = idx & 31;
            float* p = sA + r * 132 + (q << 2);
            if (r < valid) {
                int n = base + r;
                if (q < 16) {
                    float4 v = __ldg((const float4*)nf + (size_t)n * 16 + q);
                    p[0] = v.x; p[1] = v.y; p[2] = v.z; p[3] = v.w;
                } else {
                    float inv = 1.0f / fmaxf(g_cnt[n], 1.0f);
                    float4 v = *((const float4*)g_agg + (size_t)n * 16 + (q - 16));
                    p[0] = v.x * inv; p[1] = v.y * inv;
                    p[2] = v.z * inv; p[3] = v.w * inv;
                }
            } else {
                p[0] = 0.f; p[1] = 0.f; p[2] = 0.f; p[3] = 0.f;
            }
        }
        __syncthreads();

        gemm_f2<128, 132, 132, 68>(sA, sW1, sb,      sH, tid);
        gemm_f2<64,  68,  68,  68>(sH, sW2, sb + 64, sH, tid);

        for (int idx = tid; idx < 1024; idx += 256) {
            int r = idx >> 4, q = idx & 15;
            if (r < valid) {
                const float* p = sH + r * 68 + (q << 2);
                ((float4*)out)[(size_t)(base + r) * 16 + q] =
                    make_float4(p[0], p[1], p[2], p[3]);
            }
        }
        __syncthreads();
    }
}

// ---------------- launch ----------------
extern "C" void kernel_launch(void* const* d_in, const int* in_sizes, int n_in,
                              void* d_out, int out_size)
{
    int pi;
    const int *src, *dst;
    int E;
    if (in_sizes[2] > 1000) {            // dict order
        src = (const int*)d_in[2];
        dst = (const int*)d_in[3];
        E = in_sizes[2];
        pi = 4;
    } else {                              // reference order
        pi = 2;
        src = (const int*)d_in[30];
        dst = (const int*)d_in[31];
        E = in_sizes[30];
    }
    const float* nf = (const float*)d_in[0];
    const float* ef = (const float*)d_in[1];
    const int N = in_sizes[0] / 64;

    const float* P[28];
    for (int i = 0; i < 28; i++) P[i] = (const float*)d_in[pi + i];

    cudaFuncSetAttribute(msg_kernel, cudaFuncAttributeMaxDynamicSharedMemorySize,
                         MSG_SMEM_BYTES);
    cudaFuncSetAttribute(edge_kernel, cudaFuncAttributeMaxDynamicSharedMemorySize,
                         EDGE_SMEM_BYTES);
    cudaFuncSetAttribute(node_kernel, cudaFuncAttributeMaxDynamicSharedMemorySize,
                         NODE_SMEM_BYTES);

    zero_kernel<<<512, 256>>>(N);
    prep_kernel<<<1, 256>>>(P[0], P[1], P[2], P[3], P[4], P[5],
                            P[6], P[7], P[8], P[9], P[10], P[11],
                            P[12], P[14],
                            P[16], P[17], P[18], P[19], P[20], P[21],
                            P[22], P[23], P[24], P[25], P[26], P[27]);
    msg_kernel<<<296, 256, MSG_SMEM_BYTES>>>(nf, N);
    edge_kernel<<<296, 256, EDGE_SMEM_BYTES>>>(ef, src, dst, P[13], P[15], E);
    node_kernel<<<296, 256, NODE_SMEM_BYTES>>>(nf, (float*)d_out, N);
}